// round 7
// baseline (speedup 1.0000x reference)
#include <cuda_runtime.h>
#include <math.h>

#define BB 16
#define SS 1024
#define DD 1024
#define HH 16
#define DH 64

// Scratch for Q, K, V in head-split layout [B, H, S, Dh] (64 MB each).
// Q pre-scaled by 0.125; all three tf32-rounded by the GEMM epilogue.
__device__ float g_q[BB * HH * SS * DH];
__device__ float g_k[BB * HH * SS * DH];
__device__ float g_v[BB * HH * SS * DH];

// ---------------------------------------------------------------------------
__device__ __forceinline__ float to_tf32(float x) {
    float r;
    asm("cvt.rna.tf32.f32 %0, %1;" : "=f"(r) : "f"(x));
    return r;
}

__device__ __forceinline__ void mma_tf32(float* d, const unsigned* a, const unsigned* b) {
    asm volatile(
        "mma.sync.aligned.m16n8k8.row.col.f32.tf32.tf32.f32 "
        "{%0,%1,%2,%3},{%4,%5,%6,%7},{%8,%9},{%0,%1,%2,%3};"
        : "+f"(d[0]), "+f"(d[1]), "+f"(d[2]), "+f"(d[3])
        : "r"(a[0]), "r"(a[1]), "r"(a[2]), "r"(a[3]), "r"(b[0]), "r"(b[1]));
}

__device__ __forceinline__ unsigned smem_u32(const void* p) {
    return (unsigned)__cvta_generic_to_shared(p);
}
__device__ __forceinline__ void cp16(unsigned dst, const void* src) {
    asm volatile("cp.async.cg.shared.global [%0], [%1], 16;" :: "r"(dst), "l"(src));
}
__device__ __forceinline__ void cp_commit() {
    asm volatile("cp.async.commit_group;");
}
template <int N>
__device__ __forceinline__ void cp_wait() {
    asm volatile("cp.async.wait_group %0;" :: "n"(N));
}

// ---------------------------------------------------------------------------
// QKV projection (R2-proven loop): Y = to_tf32((X @ W^T + b) * scale).
// BM=BN=128, BK=32, 256 threads (8 warps as 4x2), warp tile 32x64.
// ---------------------------------------------------------------------------
__global__ __launch_bounds__(256)
void qkv_gemm(const float* __restrict__ X, const float* __restrict__ W,
              const float* __restrict__ bias, int which)
{
    __shared__ float sa[128][36];
    __shared__ float sb[128][36];

    float* __restrict__ Y = (which == 0) ? g_q : (which == 1) ? g_k : g_v;
    const float scale = (which == 0) ? 0.125f : 1.0f;

    const int tid  = threadIdx.x;
    const int lane = tid & 31;
    const int warp = tid >> 5;
    const int wm   = (warp & 3) * 32;
    const int wn   = (warp >> 2) * 64;
    const int m0   = blockIdx.y * 128;
    const int n0   = blockIdx.x * 128;

    const int lr = tid >> 3;
    const int lc = (tid & 7) * 4;

    float acc[2][8][4];
    #pragma unroll
    for (int i = 0; i < 2; i++)
        #pragma unroll
        for (int j = 0; j < 8; j++)
            #pragma unroll
            for (int c = 0; c < 4; c++) acc[i][j][c] = 0.0f;

    const int r4 = lane >> 2;
    const int c4 = lane & 3;

    for (int k0 = 0; k0 < DD; k0 += 32) {
        float4 va[4], vb[4];
        #pragma unroll
        for (int i = 0; i < 4; i++) {
            va[i] = *(const float4*)(X + (size_t)(m0 + lr + 32 * i) * DD + k0 + lc);
            vb[i] = *(const float4*)(W + (size_t)(n0 + lr + 32 * i) * DD + k0 + lc);
        }
        __syncthreads();
        #pragma unroll
        for (int i = 0; i < 4; i++) {
            sa[lr + 32 * i][lc + 0] = to_tf32(va[i].x);
            sa[lr + 32 * i][lc + 1] = to_tf32(va[i].y);
            sa[lr + 32 * i][lc + 2] = to_tf32(va[i].z);
            sa[lr + 32 * i][lc + 3] = to_tf32(va[i].w);
            sb[lr + 32 * i][lc + 0] = to_tf32(vb[i].x);
            sb[lr + 32 * i][lc + 1] = to_tf32(vb[i].y);
            sb[lr + 32 * i][lc + 2] = to_tf32(vb[i].z);
            sb[lr + 32 * i][lc + 3] = to_tf32(vb[i].w);
        }
        __syncthreads();

        #pragma unroll
        for (int ks = 0; ks < 4; ks++) {
            const int kk = ks * 8;
            unsigned af[2][4];
            #pragma unroll
            for (int mt = 0; mt < 2; mt++) {
                const int rb = wm + mt * 16;
                af[mt][0] = __float_as_uint(sa[rb + r4    ][kk + c4    ]);
                af[mt][1] = __float_as_uint(sa[rb + r4 + 8][kk + c4    ]);
                af[mt][2] = __float_as_uint(sa[rb + r4    ][kk + c4 + 4]);
                af[mt][3] = __float_as_uint(sa[rb + r4 + 8][kk + c4 + 4]);
            }
            #pragma unroll
            for (int nt = 0; nt < 8; nt++) {
                const int cb = wn + nt * 8;
                unsigned bf[2];
                bf[0] = __float_as_uint(sb[cb + r4][kk + c4    ]);
                bf[1] = __float_as_uint(sb[cb + r4][kk + c4 + 4]);
                mma_tf32(acc[0][nt], af[0], bf);
                mma_tf32(acc[1][nt], af[1], bf);
            }
        }
    }

    // Epilogue: (acc + bias) * scale, tf32-rounded, head-split scatter.
    #pragma unroll
    for (int mt = 0; mt < 2; mt++) {
        const int mA = m0 + wm + mt * 16 + r4;
        const int mB = mA + 8;
        const int bA = mA >> 10, sA_ = mA & 1023;
        const int bB = mB >> 10, sB_ = mB & 1023;
        #pragma unroll
        for (int nt = 0; nt < 8; nt++) {
            const int col = n0 + wn + nt * 8 + 2 * c4;
            const int h = col >> 6, d = col & 63;
            const float b0 = bias[col], b1 = bias[col + 1];
            float2 vA = make_float2(to_tf32((acc[mt][nt][0] + b0) * scale),
                                    to_tf32((acc[mt][nt][1] + b1) * scale));
            float2 vB = make_float2(to_tf32((acc[mt][nt][2] + b0) * scale),
                                    to_tf32((acc[mt][nt][3] + b1) * scale));
            *(float2*)(Y + (((size_t)(bA * HH + h) * SS + sA_) * DH) + d) = vA;
            *(float2*)(Y + (((size_t)(bB * HH + h) * SS + sB_) * DH) + d) = vB;
        }
    }
}

// ---------------------------------------------------------------------------
// Flash attention (R3's 32-row/warp version). Block = 128 thr (4 warps),
// 32 q-rows per warp (2 m16 tiles), BC=32, Dh=64. Q fragments in registers
// for the whole loop; K/V double-buffered cp.async; B-frags shared across
// both m-tiles (halves LDS per MMA vs 16-row).
// Dynamic smem floats: K 2*32*68, V 2*32*72, P 4*32*36 -> 54272 B
// ---------------------------------------------------------------------------
#define SK_OFF 0
#define SV_OFF (2 * 32 * 68)
#define SP_OFF (SV_OFF + 2 * 32 * 72)
#define ATTN_SMEM ((SP_OFF + 4 * 32 * 36) * 4)

__global__ __launch_bounds__(128)
void attn_kernel(float* __restrict__ out)
{
    extern __shared__ float sm[];
    float* sK[2] = { sm + SK_OFF, sm + SK_OFF + 32 * 68 };
    float* sV[2] = { sm + SV_OFF, sm + SV_OFF + 32 * 72 };

    const int tid  = threadIdx.x;
    const int lane = tid & 31;
    const int warp = tid >> 5;
    const int bh   = blockIdx.y;
    const int b    = bh >> 4;
    const int h    = bh & 15;
    const int qrow0 = blockIdx.x * 128 + warp * 32;

    const int r4 = lane >> 2;
    const int c4 = lane & 3;

    float* sPw = sm + SP_OFF + warp * (32 * 36);

    const float* __restrict__ Qb = g_q + (size_t)bh * SS * DH;
    const float* __restrict__ Kb = g_k + (size_t)bh * SS * DH;
    const float* __restrict__ Vb = g_v + (size_t)bh * SS * DH;

    // Q fragments (pre-scaled, pre-rounded in gmem) -> registers, kept all loop.
    unsigned qa[2][8][4];
    #pragma unroll
    for (int mt = 0; mt < 2; mt++) {
        const int rA = qrow0 + mt * 16 + r4;
        #pragma unroll
        for (int kt = 0; kt < 8; kt++) {
            const int cc = kt * 8 + c4;
            qa[mt][kt][0] = __float_as_uint(Qb[(size_t)rA * DH + cc]);
            qa[mt][kt][1] = __float_as_uint(Qb[(size_t)(rA + 8) * DH + cc]);
            qa[mt][kt][2] = __float_as_uint(Qb[(size_t)rA * DH + cc + 4]);
            qa[mt][kt][3] = __float_as_uint(Qb[(size_t)(rA + 8) * DH + cc + 4]);
        }
    }

    float o[2][8][4];
    #pragma unroll
    for (int mt = 0; mt < 2; mt++)
        #pragma unroll
        for (int nt = 0; nt < 8; nt++)
            #pragma unroll
            for (int c = 0; c < 4; c++) o[mt][nt][c] = 0.0f;
    float mv[2][2] = { {-INFINITY, -INFINITY}, {-INFINITY, -INFINITY} };
    float lv[2][2] = { {0.0f, 0.0f}, {0.0f, 0.0f} };

    // cp.async mapping for a 32x64 tile: row = tid>>2, colbase = (tid&3)*16
    const int prow = tid >> 2;
    const int pcb  = (tid & 3) * 16;

    // prefetch tile 0
    {
        const float* ks = Kb + (size_t)prow * DH + pcb;
        const float* vs = Vb + (size_t)prow * DH + pcb;
        unsigned dK = smem_u32(sK[0] + prow * 68 + pcb);
        unsigned dV = smem_u32(sV[0] + prow * 72 + pcb);
        #pragma unroll
        for (int i = 0; i < 4; i++) {
            cp16(dK + i * 16, ks + i * 4);
            cp16(dV + i * 16, vs + i * 4);
        }
        cp_commit();
    }

    for (int t = 0; t < 32; t++) {
        const int cur = t & 1;
        if (t < 31) {
            const size_t roff = (size_t)((t + 1) * 32 + prow) * DH + pcb;
            const float* ks = Kb + roff;
            const float* vs = Vb + roff;
            unsigned dK = smem_u32(sK[cur ^ 1] + prow * 68 + pcb);
            unsigned dV = smem_u32(sV[cur ^ 1] + prow * 72 + pcb);
            #pragma unroll
            for (int i = 0; i < 4; i++) {
                cp16(dK + i * 16, ks + i * 4);
                cp16(dV + i * 16, vs + i * 4);
            }
            cp_commit();
            cp_wait<1>();
        } else {
            cp_wait<0>();
        }
        __syncthreads();

        const float* cK = sK[cur];
        const float* cV = sV[cur];

        // S = Q @ K^T : [2 m-tiles][4 kv n-tiles], B-frags shared across m-tiles
        float s[2][4][4];
        #pragma unroll
        for (int mt = 0; mt < 2; mt++)
            #pragma unroll
            for (int nt = 0; nt < 4; nt++)
                #pragma unroll
                for (int c = 0; c < 4; c++) s[mt][nt][c] = 0.0f;
        #pragma unroll
        for (int kt = 0; kt < 8; kt++) {
            #pragma unroll
            for (int nt = 0; nt < 4; nt++) {
                unsigned bf[2];
                bf[0] = __float_as_uint(cK[(nt * 8 + r4) * 68 + kt * 8 + c4    ]);
                bf[1] = __float_as_uint(cK[(nt * 8 + r4) * 68 + kt * 8 + c4 + 4]);
                mma_tf32(s[0][nt], qa[0][kt], bf);
                mma_tf32(s[1][nt], qa[1][kt], bf);
            }
        }

        // online softmax per m-tile
        #pragma unroll
        for (int mt = 0; mt < 2; mt++) {
            float tm0 = -INFINITY, tm1 = -INFINITY;
            #pragma unroll
            for (int nt = 0; nt < 4; nt++) {
                tm0 = fmaxf(tm0, fmaxf(s[mt][nt][0], s[mt][nt][1]));
                tm1 = fmaxf(tm1, fmaxf(s[mt][nt][2], s[mt][nt][3]));
            }
            tm0 = fmaxf(tm0, __shfl_xor_sync(0xffffffffu, tm0, 1));
            tm0 = fmaxf(tm0, __shfl_xor_sync(0xffffffffu, tm0, 2));
            tm1 = fmaxf(tm1, __shfl_xor_sync(0xffffffffu, tm1, 1));
            tm1 = fmaxf(tm1, __shfl_xor_sync(0xffffffffu, tm1, 2));

            const float mn0 = fmaxf(mv[mt][0], tm0);
            const float mn1 = fmaxf(mv[mt][1], tm1);
            const float sc0 = __expf(mv[mt][0] - mn0);
            const float sc1 = __expf(mv[mt][1] - mn1);
            mv[mt][0] = mn0; mv[mt][1] = mn1;

            float ps0 = 0.0f, ps1 = 0.0f;
            #pragma unroll
            for (int nt = 0; nt < 4; nt++) {
                s[mt][nt][0] = __expf(s[mt][nt][0] - mn0);
                s[mt][nt][1] = __expf(s[mt][nt][1] - mn0);
                s[mt][nt][2] = __expf(s[mt][nt][2] - mn1);
                s[mt][nt][3] = __expf(s[mt][nt][3] - mn1);
                ps0 += s[mt][nt][0] + s[mt][nt][1];
                ps1 += s[mt][nt][2] + s[mt][nt][3];
            }
            ps0 += __shfl_xor_sync(0xffffffffu, ps0, 1);
            ps0 += __shfl_xor_sync(0xffffffffu, ps0, 2);
            ps1 += __shfl_xor_sync(0xffffffffu, ps1, 1);
            ps1 += __shfl_xor_sync(0xffffffffu, ps1, 2);
            lv[mt][0] = lv[mt][0] * sc0 + ps0;
            lv[mt][1] = lv[mt][1] * sc1 + ps1;

            #pragma unroll
            for (int nt = 0; nt < 8; nt++) {
                o[mt][nt][0] *= sc0; o[mt][nt][1] *= sc0;
                o[mt][nt][2] *= sc1; o[mt][nt][3] *= sc1;
            }

            // store P (tf32-rounded) to warp-private smem
            #pragma unroll
            for (int nt = 0; nt < 4; nt++) {
                float2 pA = make_float2(to_tf32(s[mt][nt][0]), to_tf32(s[mt][nt][1]));
                float2 pB = make_float2(to_tf32(s[mt][nt][2]), to_tf32(s[mt][nt][3]));
                *(float2*)&sPw[(mt * 16 + r4    ) * 36 + nt * 8 + 2 * c4] = pA;
                *(float2*)&sPw[(mt * 16 + r4 + 8) * 36 + nt * 8 + 2 * c4] = pB;
            }
        }
        __syncwarp();

        // P A-fragments
        unsigned pa[2][4][4];
        #pragma unroll
        for (int mt = 0; mt < 2; mt++)
            #pragma unroll
            for (int kt = 0; kt < 4; kt++) {
                pa[mt][kt][0] = __float_as_uint(sPw[(mt * 16 + r4    ) * 36 + kt * 8 + c4    ]);
                pa[mt][kt][1] = __float_as_uint(sPw[(mt * 16 + r4 + 8) * 36 + kt * 8 + c4    ]);
                pa[mt][kt][2] = __float_as_uint(sPw[(mt * 16 + r4    ) * 36 + kt * 8 + c4 + 4]);
                pa[mt][kt][3] = __float_as_uint(sPw[(mt * 16 + r4 + 8) * 36 + kt * 8 + c4 + 4]);
            }

        // O += P @ V  (B-frags shared across m-tiles)
        #pragma unroll
        for (int nt = 0; nt < 8; nt++) {
            #pragma unroll
            for (int kt = 0; kt < 4; kt++) {
                unsigned bf[2];
                bf[0] = __float_as_uint(cV[(kt * 8 + c4    ) * 72 + nt * 8 + r4]);
                bf[1] = __float_as_uint(cV[(kt * 8 + c4 + 4) * 72 + nt * 8 + r4]);
                mma_tf32(o[0][nt], pa[0][kt], bf);
                mma_tf32(o[1][nt], pa[1][kt], bf);
            }
        }
        __syncthreads();
    }

    // epilogue
    #pragma unroll
    for (int mt = 0; mt < 2; mt++) {
        const float inv0 = 1.0f / lv[mt][0];
        const float inv1 = 1.0f / lv[mt][1];
        const int rA = qrow0 + mt * 16 + r4;
        const int rB = rA + 8;
        float* oA = out + ((size_t)(b * SS + rA)) * DD + h * DH;
        float* oB = out + ((size_t)(b * SS + rB)) * DD + h * DH;
        #pragma unroll
        for (int nt = 0; nt < 8; nt++) {
            const int d = nt * 8 + 2 * c4;
            *(float2*)(oA + d) = make_float2(o[mt][nt][0] * inv0, o[mt][nt][1] * inv0);
            *(float2*)(oB + d) = make_float2(o[mt][nt][2] * inv1, o[mt][nt][3] * inv1);
        }
    }
}

// ---------------------------------------------------------------------------
extern "C" void kernel_launch(void* const* d_in, const int* in_sizes, int n_in,
                              void* d_out, int out_size)
{
    const float* x  = (const float*)d_in[0];
    const float* Wq = (const float*)d_in[1];
    const float* bq = (const float*)d_in[2];
    const float* Wk = (const float*)d_in[3];
    const float* bk = (const float*)d_in[4];
    const float* Wv = (const float*)d_in[5];
    const float* bv = (const float*)d_in[6];
    float* out = (float*)d_out;

    cudaFuncSetAttribute(attn_kernel, cudaFuncAttributeMaxDynamicSharedMemorySize, ATTN_SMEM);

    dim3 gg(DD / 128, (BB * SS) / 128);   // (8, 128)
    qkv_gemm<<<gg, 256>>>(x, Wq, bq, 0);
    qkv_gemm<<<gg, 256>>>(x, Wk, bk, 1);
    qkv_gemm<<<gg, 256>>>(x, Wv, bv, 2);

    dim3 ga(SS / 128, BB * HH);           // (8, 256)
    attn_kernel<<<ga, 128, ATTN_SMEM>>>(out);
}

// round 8
// speedup vs baseline: 1.2770x; 1.2770x over previous
#include <cuda_runtime.h>
#include <math.h>

#define BB 16
#define SS 1024
#define DD 1024
#define HH 16
#define DH 64

// Device scratch (no allocations allowed).
__device__ float g_q[BB * HH * SS * DH];   // pre-scaled by 0.125, tf32-rounded
__device__ float g_k[BB * HH * SS * DH];   // tf32-rounded
__device__ float g_v[BB * HH * SS * DH];   // tf32-rounded
__device__ float g_x[BB * SS * DD];        // tf32-rounded X
__device__ float g_w[3 * DD * DD];         // tf32-rounded Wq,Wk,Wv

// ---------------------------------------------------------------------------
__device__ __forceinline__ float to_tf32(float x) {
    float r;
    asm("cvt.rna.tf32.f32 %0, %1;" : "=f"(r) : "f"(x));
    return r;
}

__device__ __forceinline__ void mma_tf32(float* d, const unsigned* a, const unsigned* b) {
    asm volatile(
        "mma.sync.aligned.m16n8k8.row.col.f32.tf32.tf32.f32 "
        "{%0,%1,%2,%3},{%4,%5,%6,%7},{%8,%9},{%0,%1,%2,%3};"
        : "+f"(d[0]), "+f"(d[1]), "+f"(d[2]), "+f"(d[3])
        : "r"(a[0]), "r"(a[1]), "r"(a[2]), "r"(a[3]), "r"(b[0]), "r"(b[1]));
}

__device__ __forceinline__ unsigned smem_u32(const void* p) {
    return (unsigned)__cvta_generic_to_shared(p);
}
__device__ __forceinline__ void cp16(unsigned dst, const void* src) {
    asm volatile("cp.async.cg.shared.global [%0], [%1], 16;" :: "r"(dst), "l"(src));
}
__device__ __forceinline__ void cp_commit() {
    asm volatile("cp.async.commit_group;");
}
template <int N>
__device__ __forceinline__ void cp_wait() {
    asm volatile("cp.async.wait_group %0;" :: "n"(N));
}

// ---------------------------------------------------------------------------
// Pre-pass: tf32-round a buffer (float4).
// ---------------------------------------------------------------------------
__global__ void round_copy(float* __restrict__ dst, const float* __restrict__ src, int n4)
{
    int i = blockIdx.x * blockDim.x + threadIdx.x;
    if (i < n4) {
        float4 v = ((const float4*)src)[i];
        v.x = to_tf32(v.x); v.y = to_tf32(v.y); v.z = to_tf32(v.z); v.w = to_tf32(v.w);
        ((float4*)dst)[i] = v;
    }
}

// ---------------------------------------------------------------------------
// Fused QKV GEMM, warp tile 64x64: Y = to_tf32((X @ W^T + b) * scale).
// BM=128, BN=256, BK=32, 256 thr (8 warps as 2m x 4n), 2-stage cp.async.
// grid (12, 128): wsel = bx>>2, n0 = (bx&3)*256.
// smem/stage: A 128x36 + B 256x36 floats; 2 stages = 110592 B.
// ---------------------------------------------------------------------------
#define GSTAGE (128 * 36 + 256 * 36)          // floats per stage
#define GEMM_SMEM (2 * GSTAGE * 4)            // bytes

__global__ __launch_bounds__(256, 1)
void qkv_gemm(const float* __restrict__ bq, const float* __restrict__ bk,
              const float* __restrict__ bv)
{
    extern __shared__ float sm[];

    const int tid  = threadIdx.x;
    const int lane = tid & 31;
    const int warp = tid >> 5;
    const int bx   = blockIdx.x;
    const int wsel = bx >> 2;
    const int n0   = (bx & 3) * 256;
    const int m0   = blockIdx.y * 128;

    const float* __restrict__ Wm   = g_w + (size_t)wsel * DD * DD;
    const float* __restrict__ bias = (wsel == 0) ? bq : (wsel == 1) ? bk : bv;
    float* __restrict__ Y = (wsel == 0) ? g_q : (wsel == 1) ? g_k : g_v;
    const float scale = (wsel == 0) ? 0.125f : 1.0f;

    const int wm = (warp & 1) * 64;    // 2 warps in m
    const int wn = (warp >> 1) * 64;   // 4 warps in n
    const int r4 = lane >> 2;
    const int c4 = lane & 3;

    // load maps
    const int a_r  = tid >> 1;          // 0..127
    const int a_cb = (tid & 1) * 16;    // float col base, 4 x cp16
    const float* srcA = g_x + (size_t)(m0 + a_r) * DD + a_cb;
    const float* srcB = Wm  + (size_t)(n0 + tid) * DD;   // 8 x cp16 across row

    float acc[4][8][4];
    #pragma unroll
    for (int i = 0; i < 4; i++)
        #pragma unroll
        for (int j = 0; j < 8; j++)
            #pragma unroll
            for (int c = 0; c < 4; c++) acc[i][j][c] = 0.0f;

    // prefetch stage 0
    {
        float* sa = sm;
        float* sb = sm + 128 * 36;
        unsigned dA = smem_u32(sa + a_r * 36 + a_cb);
        unsigned dB = smem_u32(sb + tid * 36);
        #pragma unroll
        for (int i = 0; i < 4; i++) cp16(dA + i * 16, srcA + i * 4);
        #pragma unroll
        for (int i = 0; i < 8; i++) cp16(dB + i * 16, srcB + i * 4);
        cp_commit();
    }

    for (int kt = 0; kt < 32; kt++) {
        const int cur = kt & 1;
        cp_wait<0>();
        __syncthreads();   // stage `cur` ready; all warps done reading `cur^1`

        if (kt < 31) {     // prefetch next tile into cur^1 (race-free: after sync)
            const int k0 = (kt + 1) * 32;
            float* sa = sm + (cur ^ 1) * GSTAGE;
            float* sb = sa + 128 * 36;
            unsigned dA = smem_u32(sa + a_r * 36 + a_cb);
            unsigned dB = smem_u32(sb + tid * 36);
            #pragma unroll
            for (int i = 0; i < 4; i++) cp16(dA + i * 16, srcA + k0 + i * 4);
            #pragma unroll
            for (int i = 0; i < 8; i++) cp16(dB + i * 16, srcB + k0 + i * 4);
            cp_commit();
        }

        const float* cA = sm + cur * GSTAGE;
        const float* cB = cA + 128 * 36;

        #pragma unroll
        for (int ks = 0; ks < 4; ks++) {
            const int kk = ks * 8;
            unsigned af[4][4];
            #pragma unroll
            for (int mt = 0; mt < 4; mt++) {
                const int rb = wm + mt * 16;
                af[mt][0] = __float_as_uint(cA[(rb + r4    ) * 36 + kk + c4    ]);
                af[mt][1] = __float_as_uint(cA[(rb + r4 + 8) * 36 + kk + c4    ]);
                af[mt][2] = __float_as_uint(cA[(rb + r4    ) * 36 + kk + c4 + 4]);
                af[mt][3] = __float_as_uint(cA[(rb + r4 + 8) * 36 + kk + c4 + 4]);
            }
            #pragma unroll
            for (int nt = 0; nt < 8; nt++) {
                const int cb = wn + nt * 8;
                unsigned bf[2];
                bf[0] = __float_as_uint(cB[(cb + r4) * 36 + kk + c4    ]);
                bf[1] = __float_as_uint(cB[(cb + r4) * 36 + kk + c4 + 4]);
                #pragma unroll
                for (int mt = 0; mt < 4; mt++)
                    mma_tf32(acc[mt][nt], af[mt], bf);
            }
        }
    }

    // Epilogue: (acc + bias) * scale, tf32-rounded, head-split scatter.
    #pragma unroll
    for (int mt = 0; mt < 4; mt++) {
        const int mA = m0 + wm + mt * 16 + r4;
        const int mB = mA + 8;
        const int bA = mA >> 10, sA_ = mA & 1023;
        const int bB = mB >> 10, sB_ = mB & 1023;
        #pragma unroll
        for (int nt = 0; nt < 8; nt++) {
            const int col = n0 + wn + nt * 8 + 2 * c4;
            const int h = col >> 6, d = col & 63;
            const float b0 = bias[col], b1 = bias[col + 1];
            float2 vA = make_float2(to_tf32((acc[mt][nt][0] + b0) * scale),
                                    to_tf32((acc[mt][nt][1] + b1) * scale));
            float2 vB = make_float2(to_tf32((acc[mt][nt][2] + b0) * scale),
                                    to_tf32((acc[mt][nt][3] + b1) * scale));
            *(float2*)(Y + (((size_t)(bA * HH + h) * SS + sA_) * DH) + d) = vA;
            *(float2*)(Y + (((size_t)(bB * HH + h) * SS + sB_) * DH) + d) = vB;
        }
    }
}

// ---------------------------------------------------------------------------
// Flash attention — byte-identical to R2/R6 (measured 561-566us), except Q is
// already pre-scaled & rounded in g_q so staging drops the *0.125 (values
// identical: epilogue applied the same op).
// ---------------------------------------------------------------------------
__global__ __launch_bounds__(128)
void attn_kernel(float* __restrict__ out)
{
    __shared__ float sk[32][68];
    __shared__ float sv[32][72];
    __shared__ float sp[4][16][68];

    const int tid  = threadIdx.x;
    const int lane = tid & 31;
    const int warp = tid >> 5;
    const int bh   = blockIdx.y;
    const int b    = bh >> 4;
    const int h    = bh & 15;
    const int qrow0 = blockIdx.x * 64 + warp * 16;

    const int r4 = lane >> 2;
    const int c4 = lane & 3;

    const float* Qb = g_q + (size_t)bh * SS * DH;
    const float* Kb = g_k + (size_t)bh * SS * DH;
    const float* Vb = g_v + (size_t)bh * SS * DH;

    // stage Q into sp[warp] (already scaled+rounded), load fragments
    {
        #pragma unroll
        for (int i = 0; i < 8; i++) {
            const int idx = lane + i * 32;
            const int row = idx >> 4;
            const int cc  = (idx & 15) * 4;
            float4 t = *(const float4*)(Qb + (size_t)(qrow0 + row) * DH + cc);
            *(float4*)&sp[warp][row][cc] = t;
        }
    }
    __syncwarp();
    unsigned qa[8][4];
    #pragma unroll
    for (int kt = 0; kt < 8; kt++) {
        qa[kt][0] = __float_as_uint(sp[warp][r4    ][kt * 8 + c4    ]);
        qa[kt][1] = __float_as_uint(sp[warp][r4 + 8][kt * 8 + c4    ]);
        qa[kt][2] = __float_as_uint(sp[warp][r4    ][kt * 8 + c4 + 4]);
        qa[kt][3] = __float_as_uint(sp[warp][r4 + 8][kt * 8 + c4 + 4]);
    }
    __syncwarp();

    float o[8][4];
    #pragma unroll
    for (int nt = 0; nt < 8; nt++)
        #pragma unroll
        for (int c = 0; c < 4; c++) o[nt][c] = 0.0f;
    float m0v = -INFINITY, m1v = -INFINITY;
    float l0 = 0.0f, l1 = 0.0f;

    for (int t0 = 0; t0 < SS; t0 += 32) {
        __syncthreads();
        #pragma unroll
        for (int i = 0; i < 4; i++) {
            const int idx = tid + i * 128;
            const int row = idx >> 4;
            const int cc  = (idx & 15) * 4;
            float4 kt4 = *(const float4*)(Kb + (size_t)(t0 + row) * DH + cc);
            float4 vt4 = *(const float4*)(Vb + (size_t)(t0 + row) * DH + cc);
            *(float4*)&sk[row][cc] = kt4;
            *(float4*)&sv[row][cc] = vt4;
        }
        __syncthreads();

        float s[4][4];
        #pragma unroll
        for (int nt = 0; nt < 4; nt++) {
            #pragma unroll
            for (int c = 0; c < 4; c++) s[nt][c] = 0.0f;
            #pragma unroll
            for (int kt = 0; kt < 8; kt++) {
                unsigned bf[2];
                bf[0] = __float_as_uint(sk[nt * 8 + r4][kt * 8 + c4    ]);
                bf[1] = __float_as_uint(sk[nt * 8 + r4][kt * 8 + c4 + 4]);
                mma_tf32(s[nt], qa[kt], bf);
            }
        }

        float tm0 = -INFINITY, tm1 = -INFINITY;
        #pragma unroll
        for (int nt = 0; nt < 4; nt++) {
            tm0 = fmaxf(tm0, fmaxf(s[nt][0], s[nt][1]));
            tm1 = fmaxf(tm1, fmaxf(s[nt][2], s[nt][3]));
        }
        tm0 = fmaxf(tm0, __shfl_xor_sync(0xffffffffu, tm0, 1));
        tm0 = fmaxf(tm0, __shfl_xor_sync(0xffffffffu, tm0, 2));
        tm1 = fmaxf(tm1, __shfl_xor_sync(0xffffffffu, tm1, 1));
        tm1 = fmaxf(tm1, __shfl_xor_sync(0xffffffffu, tm1, 2));

        const float mn0 = fmaxf(m0v, tm0);
        const float mn1 = fmaxf(m1v, tm1);
        const float sc0 = __expf(m0v - mn0);
        const float sc1 = __expf(m1v - mn1);
        m0v = mn0; m1v = mn1;

        float ps0 = 0.0f, ps1 = 0.0f;
        #pragma unroll
        for (int nt = 0; nt < 4; nt++) {
            s[nt][0] = __expf(s[nt][0] - mn0);
            s[nt][1] = __expf(s[nt][1] - mn0);
            s[nt][2] = __expf(s[nt][2] - mn1);
            s[nt][3] = __expf(s[nt][3] - mn1);
            ps0 += s[nt][0] + s[nt][1];
            ps1 += s[nt][2] + s[nt][3];
        }
        ps0 += __shfl_xor_sync(0xffffffffu, ps0, 1);
        ps0 += __shfl_xor_sync(0xffffffffu, ps0, 2);
        ps1 += __shfl_xor_sync(0xffffffffu, ps1, 1);
        ps1 += __shfl_xor_sync(0xffffffffu, ps1, 2);
        l0 = l0 * sc0 + ps0;
        l1 = l1 * sc1 + ps1;

        #pragma unroll
        for (int nt = 0; nt < 8; nt++) {
            o[nt][0] *= sc0; o[nt][1] *= sc0;
            o[nt][2] *= sc1; o[nt][3] *= sc1;
        }

        #pragma unroll
        for (int nt = 0; nt < 4; nt++) {
            float2 pA = make_float2(to_tf32(s[nt][0]), to_tf32(s[nt][1]));
            float2 pB = make_float2(to_tf32(s[nt][2]), to_tf32(s[nt][3]));
            *(float2*)&sp[warp][r4    ][nt * 8 + 2 * c4] = pA;
            *(float2*)&sp[warp][r4 + 8][nt * 8 + 2 * c4] = pB;
        }
        __syncwarp();

        unsigned pa[4][4];
        #pragma unroll
        for (int kt = 0; kt < 4; kt++) {
            pa[kt][0] = __float_as_uint(sp[warp][r4    ][kt * 8 + c4    ]);
            pa[kt][1] = __float_as_uint(sp[warp][r4 + 8][kt * 8 + c4    ]);
            pa[kt][2] = __float_as_uint(sp[warp][r4    ][kt * 8 + c4 + 4]);
            pa[kt][3] = __float_as_uint(sp[warp][r4 + 8][kt * 8 + c4 + 4]);
        }
        #pragma unroll
        for (int nt = 0; nt < 8; nt++) {
            #pragma unroll
            for (int kt = 0; kt < 4; kt++) {
                unsigned bf[2];
                bf[0] = __float_as_uint(sv[kt * 8 + c4    ][nt * 8 + r4]);
                bf[1] = __float_as_uint(sv[kt * 8 + c4 + 4][nt * 8 + r4]);
                mma_tf32(o[nt], pa[kt], bf);
            }
        }
        __syncwarp();
    }

    const float inv0 = 1.0f / l0;
    const float inv1 = 1.0f / l1;
    const int rA = qrow0 + r4;
    const int rB = rA + 8;
    float* oA = out + ((size_t)(b * SS + rA)) * DD + h * DH;
    float* oB = out + ((size_t)(b * SS + rB)) * DD + h * DH;
    #pragma unroll
    for (int nt = 0; nt < 8; nt++) {
        const int d = nt * 8 + 2 * c4;
        *(float2*)(oA + d) = make_float2(o[nt][0] * inv0, o[nt][1] * inv0);
        *(float2*)(oB + d) = make_float2(o[nt][2] * inv1, o[nt][3] * inv1);
    }
}

// ---------------------------------------------------------------------------
extern "C" void kernel_launch(void* const* d_in, const int* in_sizes, int n_in,
                              void* d_out, int out_size)
{
    const float* x  = (const float*)d_in[0];
    const float* Wq = (const float*)d_in[1];
    const float* bq = (const float*)d_in[2];
    const float* Wk = (const float*)d_in[3];
    const float* bk = (const float*)d_in[4];
    const float* Wv = (const float*)d_in[5];
    const float* bv = (const float*)d_in[6];
    float* out = (float*)d_out;

    cudaFuncSetAttribute(qkv_gemm, cudaFuncAttributeMaxDynamicSharedMemorySize, GEMM_SMEM);

    float* gx; cudaGetSymbolAddress((void**)&gx, g_x);
    float* gw; cudaGetSymbolAddress((void**)&gw, g_w);

    round_copy<<<(BB * SS * DD / 4 + 255) / 256, 256>>>(gx, x, BB * SS * DD / 4);
    round_copy<<<(DD * DD / 4 + 255) / 256, 256>>>(gw,               Wq, DD * DD / 4);
    round_copy<<<(DD * DD / 4 + 255) / 256, 256>>>(gw + DD * DD,     Wk, DD * DD / 4);
    round_copy<<<(DD * DD / 4 + 255) / 256, 256>>>(gw + 2 * DD * DD, Wv, DD * DD / 4);

    dim3 gg(12, 128);
    qkv_gemm<<<gg, 256, GEMM_SMEM>>>(bq, bk, bv);

    dim3 ga(SS / 64, BB * HH);   // (16, 256)
    attn_kernel<<<ga, 128>>>(out);
}

// round 10
// speedup vs baseline: 1.5311x; 1.1990x over previous
#include <cuda_runtime.h>
#include <cuda_fp16.h>
#include <math.h>

#define BB 16
#define SS 1024
#define DD 1024
#define HH 16
#define DH 64

// Scratch for Q, K, V in head-split layout [B, H, S, Dh] (fp32; attention
// converts to fp16 at staging, applying the 1/8 score scale to Q).
__device__ float g_q[BB * HH * SS * DH];
__device__ float g_k[BB * HH * SS * DH];
__device__ float g_v[BB * HH * SS * DH];

// ---------------------------------------------------------------------------
// d += a @ b   (m16n8k16 fp16 inputs, fp32 accumulate)
// ---------------------------------------------------------------------------
__device__ __forceinline__ void mma_f16(float* d, const unsigned* a, const unsigned* b) {
    asm volatile(
        "mma.sync.aligned.m16n8k16.row.col.f32.f16.f16.f32 "
        "{%0,%1,%2,%3},{%4,%5,%6,%7},{%8,%9},{%0,%1,%2,%3};"
        : "+f"(d[0]), "+f"(d[1]), "+f"(d[2]), "+f"(d[3])
        : "r"(a[0]), "r"(a[1]), "r"(a[2]), "r"(a[3]), "r"(b[0]), "r"(b[1]));
}

__device__ __forceinline__ unsigned h2u(__half2 h) {
    return *(unsigned*)&h;
}

// ---------------------------------------------------------------------------
// QKV projection: Y = X @ W^T + b (fp32 out). fp16 m16n8k16 mma.
// BM=BN=128, BK=32, 256 threads (8 warps as 4x2), warp tile 32x64.
// smem halfs stride 40 (bank-verified conflict-free fragment loads).
// ---------------------------------------------------------------------------
__global__ __launch_bounds__(256)
void qkv_gemm(const float* __restrict__ X, const float* __restrict__ W,
              const float* __restrict__ bias, int which)
{
    __shared__ __half sa[128][40];   // [m][k]
    __shared__ __half sb[128][40];   // [n][k]

    float* __restrict__ Y = (which == 0) ? g_q : (which == 1) ? g_k : g_v;

    const int tid  = threadIdx.x;
    const int lane = tid & 31;
    const int warp = tid >> 5;
    const int wm   = (warp & 3) * 32;
    const int wn   = (warp >> 2) * 64;
    const int m0   = blockIdx.y * 128;
    const int n0   = blockIdx.x * 128;

    // staging map: row = tid>>1 (0..127), half-col base hb = (tid&1)*16
    const int lrow = tid >> 1;
    const int hb   = (tid & 1) * 16;
    const float* pa = X + (size_t)(m0 + lrow) * DD + hb;
    const float* pb = W + (size_t)(n0 + lrow) * DD + hb;

    const int r4 = lane >> 2;
    const int c4 = lane & 3;

    float acc[2][8][4];
    #pragma unroll
    for (int i = 0; i < 2; i++)
        #pragma unroll
        for (int j = 0; j < 8; j++)
            #pragma unroll
            for (int c = 0; c < 4; c++) acc[i][j][c] = 0.0f;

    for (int k0 = 0; k0 < DD; k0 += 32) {
        float4 va[4], vb[4];
        #pragma unroll
        for (int j = 0; j < 4; j++) {
            va[j] = *(const float4*)(pa + k0 + 4 * j);
            vb[j] = *(const float4*)(pb + k0 + 4 * j);
        }
        __syncthreads();
        {
            // pack 16 floats -> 8 half2 -> two 16B stores per side
            unsigned ha[8], hbx[8];
            #pragma unroll
            for (int j = 0; j < 4; j++) {
                ha[2*j]    = h2u(__floats2half2_rn(va[j].x, va[j].y));
                ha[2*j+1]  = h2u(__floats2half2_rn(va[j].z, va[j].w));
                hbx[2*j]   = h2u(__floats2half2_rn(vb[j].x, vb[j].y));
                hbx[2*j+1] = h2u(__floats2half2_rn(vb[j].z, vb[j].w));
            }
            *(uint4*)&sa[lrow][hb]     = make_uint4(ha[0], ha[1], ha[2], ha[3]);
            *(uint4*)&sa[lrow][hb + 8] = make_uint4(ha[4], ha[5], ha[6], ha[7]);
            *(uint4*)&sb[lrow][hb]     = make_uint4(hbx[0], hbx[1], hbx[2], hbx[3]);
            *(uint4*)&sb[lrow][hb + 8] = make_uint4(hbx[4], hbx[5], hbx[6], hbx[7]);
        }
        __syncthreads();

        #pragma unroll
        for (int ks = 0; ks < 2; ks++) {          // 2 x k16 per BK=32
            const int kk = ks * 16 + 2 * c4;
            unsigned af[2][4];
            #pragma unroll
            for (int mt = 0; mt < 2; mt++) {
                const int rb = wm + mt * 16;
                af[mt][0] = *(const unsigned*)&sa[rb + r4    ][kk    ];
                af[mt][1] = *(const unsigned*)&sa[rb + r4 + 8][kk    ];
                af[mt][2] = *(const unsigned*)&sa[rb + r4    ][kk + 8];
                af[mt][3] = *(const unsigned*)&sa[rb + r4 + 8][kk + 8];
            }
            #pragma unroll
            for (int nt = 0; nt < 8; nt++) {
                const int cb = wn + nt * 8;
                unsigned bf[2];
                bf[0] = *(const unsigned*)&sb[cb + r4][kk    ];
                bf[1] = *(const unsigned*)&sb[cb + r4][kk + 8];
                mma_f16(acc[0][nt], af[0], bf);
                mma_f16(acc[1][nt], af[1], bf);
            }
        }
    }

    // Epilogue: bias + head-split scatter (fp32).
    #pragma unroll
    for (int mt = 0; mt < 2; mt++) {
        const int mA = m0 + wm + mt * 16 + r4;
        const int mB = mA + 8;
        const int bA = mA >> 10, sA_ = mA & 1023;
        const int bB = mB >> 10, sB_ = mB & 1023;
        #pragma unroll
        for (int nt = 0; nt < 8; nt++) {
            const int col = n0 + wn + nt * 8 + 2 * c4;
            const int h = col >> 6, d = col & 63;
            const float b0 = bias[col], b1 = bias[col + 1];
            float2 vA = make_float2(acc[mt][nt][0] + b0, acc[mt][nt][1] + b1);
            float2 vB = make_float2(acc[mt][nt][2] + b0, acc[mt][nt][3] + b1);
            *(float2*)(Y + (((size_t)(bA * HH + h) * SS + sA_) * DH) + d) = vA;
            *(float2*)(Y + (((size_t)(bB * HH + h) * SS + sB_) * DH) + d) = vB;
        }
    }
}

// ---------------------------------------------------------------------------
// Flash attention, fp16 m16n8k16 mma. Block = 128 thr (4 warps), 16 q-rows
// per warp, BC=32, Dh=64. fp32 softmax + fp32 O accumulators.
// sk: K tile halfs [32][72]; sv2: V pair-interleaved half2 words [16][72]
// (sv2[kvp][d] = {V[2kvp][d], V[2kvp+1][d]}); sp: per-warp Q-then-P halfs.
// All fragment loads verified conflict-free.
// ---------------------------------------------------------------------------
__global__ __launch_bounds__(128)
void attn_kernel(float* __restrict__ out)
{
    __shared__ __half sk[32][72];
    __shared__ unsigned sv2[16][72];
    __shared__ __half sp[4][16][72];

    const int tid  = threadIdx.x;
    const int lane = tid & 31;
    const int warp = tid >> 5;
    const int bh   = blockIdx.y;
    const int b    = bh >> 4;
    const int h    = bh & 15;
    const int qrow0 = blockIdx.x * 64 + warp * 16;

    const int r4 = lane >> 2;
    const int c4 = lane & 3;

    const float* Qb = g_q + (size_t)bh * SS * DH;
    const float* Kb = g_k + (size_t)bh * SS * DH;
    const float* Vb = g_v + (size_t)bh * SS * DH;

    // stage Q (x 0.125, fp16) into sp[warp], then load fragments to registers
    {
        #pragma unroll
        for (int i = 0; i < 8; i++) {
            const int idx = lane + i * 32;          // 0..255
            const int row = idx >> 4;               // 0..15
            const int cc  = (idx & 15) * 4;
            float4 t = *(const float4*)(Qb + (size_t)(qrow0 + row) * DH + cc);
            unsigned h0 = h2u(__floats2half2_rn(t.x * 0.125f, t.y * 0.125f));
            unsigned h1 = h2u(__floats2half2_rn(t.z * 0.125f, t.w * 0.125f));
            *(uint2*)&sp[warp][row][cc] = make_uint2(h0, h1);
        }
    }
    __syncwarp();
    unsigned qa[4][4];                              // 4 k16 steps over Dh=64
    #pragma unroll
    for (int ks = 0; ks < 4; ks++) {
        const int kk = ks * 16 + 2 * c4;
        qa[ks][0] = *(const unsigned*)&sp[warp][r4    ][kk    ];
        qa[ks][1] = *(const unsigned*)&sp[warp][r4 + 8][kk    ];
        qa[ks][2] = *(const unsigned*)&sp[warp][r4    ][kk + 8];
        qa[ks][3] = *(const unsigned*)&sp[warp][r4 + 8][kk + 8];
    }
    __syncwarp();

    float o[8][4];
    #pragma unroll
    for (int nt = 0; nt < 8; nt++)
        #pragma unroll
        for (int c = 0; c < 4; c++) o[nt][c] = 0.0f;
    float m0v = -INFINITY, m1v = -INFINITY;
    float l0 = 0.0f, l1 = 0.0f;

    for (int t0 = 0; t0 < SS; t0 += 32) {
        __syncthreads();
        // K: thread -> (row, 4 d's): cvt + 8B store
        #pragma unroll
        for (int i = 0; i < 4; i++) {
            const int idx = tid + i * 128;          // 0..511
            const int row = idx >> 4;               // 0..31
            const int cc  = (idx & 15) * 4;
            float4 kt4 = *(const float4*)(Kb + (size_t)(t0 + row) * DH + cc);
            unsigned h0 = h2u(__floats2half2_rn(kt4.x, kt4.y));
            unsigned h1 = h2u(__floats2half2_rn(kt4.z, kt4.w));
            *(uint2*)&sk[row][cc] = make_uint2(h0, h1);
        }
        // V: thread -> (kv pair kvp = tid>>3, 8 d's): pair-interleave, 2x16B store
        {
            const int kvp = tid >> 3;               // 0..15
            const int d0  = (tid & 7) * 8;
            const float* v0 = Vb + (size_t)(t0 + 2 * kvp) * DH + d0;
            const float* v1 = v0 + DH;
            float4 a0 = *(const float4*)(v0);
            float4 a1 = *(const float4*)(v0 + 4);
            float4 b0 = *(const float4*)(v1);
            float4 b1 = *(const float4*)(v1 + 4);
            uint4 w0, w1;
            w0.x = h2u(__floats2half2_rn(a0.x, b0.x));
            w0.y = h2u(__floats2half2_rn(a0.y, b0.y));
            w0.z = h2u(__floats2half2_rn(a0.z, b0.z));
            w0.w = h2u(__floats2half2_rn(a0.w, b0.w));
            w1.x = h2u(__floats2half2_rn(a1.x, b1.x));
            w1.y = h2u(__floats2half2_rn(a1.y, b1.y));
            w1.z = h2u(__floats2half2_rn(a1.z, b1.z));
            w1.w = h2u(__floats2half2_rn(a1.w, b1.w));
            *(uint4*)&sv2[kvp][d0]     = w0;
            *(uint4*)&sv2[kvp][d0 + 4] = w1;
        }
        __syncthreads();

        // S = Q @ K^T : 4 kv n-tiles x 4 k16 steps
        float s[4][4];
        #pragma unroll
        for (int nt = 0; nt < 4; nt++) {
            #pragma unroll
            for (int c = 0; c < 4; c++) s[nt][c] = 0.0f;
            #pragma unroll
            for (int ks = 0; ks < 4; ks++) {
                const int kk = ks * 16 + 2 * c4;
                unsigned bf[2];
                bf[0] = *(const unsigned*)&sk[nt * 8 + r4][kk    ];
                bf[1] = *(const unsigned*)&sk[nt * 8 + r4][kk + 8];
                mma_f16(s[nt], qa[ks], bf);
            }
        }

        // online softmax (fp32)
        float tm0 = -INFINITY, tm1 = -INFINITY;
        #pragma unroll
        for (int nt = 0; nt < 4; nt++) {
            tm0 = fmaxf(tm0, fmaxf(s[nt][0], s[nt][1]));
            tm1 = fmaxf(tm1, fmaxf(s[nt][2], s[nt][3]));
        }
        tm0 = fmaxf(tm0, __shfl_xor_sync(0xffffffffu, tm0, 1));
        tm0 = fmaxf(tm0, __shfl_xor_sync(0xffffffffu, tm0, 2));
        tm1 = fmaxf(tm1, __shfl_xor_sync(0xffffffffu, tm1, 1));
        tm1 = fmaxf(tm1, __shfl_xor_sync(0xffffffffu, tm1, 2));

        const float mn0 = fmaxf(m0v, tm0);
        const float mn1 = fmaxf(m1v, tm1);
        const float sc0 = __expf(m0v - mn0);
        const float sc1 = __expf(m1v - mn1);
        m0v = mn0; m1v = mn1;

        float ps0 = 0.0f, ps1 = 0.0f;
        #pragma unroll
        for (int nt = 0; nt < 4; nt++) {
            s[nt][0] = __expf(s[nt][0] - mn0);
            s[nt][1] = __expf(s[nt][1] - mn0);
            s[nt][2] = __expf(s[nt][2] - mn1);
            s[nt][3] = __expf(s[nt][3] - mn1);
            ps0 += s[nt][0] + s[nt][1];
            ps1 += s[nt][2] + s[nt][3];
        }
        ps0 += __shfl_xor_sync(0xffffffffu, ps0, 1);
        ps0 += __shfl_xor_sync(0xffffffffu, ps0, 2);
        ps1 += __shfl_xor_sync(0xffffffffu, ps1, 1);
        ps1 += __shfl_xor_sync(0xffffffffu, ps1, 2);
        l0 = l0 * sc0 + ps0;
        l1 = l1 * sc1 + ps1;

        #pragma unroll
        for (int nt = 0; nt < 8; nt++) {
            o[nt][0] *= sc0; o[nt][1] *= sc0;
            o[nt][2] *= sc1; o[nt][3] *= sc1;
        }

        // P (fp16) -> warp-private smem; reload as A fragments
        #pragma unroll
        for (int nt = 0; nt < 4; nt++) {
            const int pc = nt * 8 + 2 * c4;
            *(unsigned*)&sp[warp][r4    ][pc] = h2u(__floats2half2_rn(s[nt][0], s[nt][1]));
            *(unsigned*)&sp[warp][r4 + 8][pc] = h2u(__floats2half2_rn(s[nt][2], s[nt][3]));
        }
        __syncwarp();

        unsigned pa[2][4];                          // 2 k16 steps over kv=32
        #pragma unroll
        for (int ks = 0; ks < 2; ks++) {
            const int kk = ks * 16 + 2 * c4;
            pa[ks][0] = *(const unsigned*)&sp[warp][r4    ][kk    ];
            pa[ks][1] = *(const unsigned*)&sp[warp][r4 + 8][kk    ];
            pa[ks][2] = *(const unsigned*)&sp[warp][r4    ][kk + 8];
            pa[ks][3] = *(const unsigned*)&sp[warp][r4 + 8][kk + 8];
        }

        // O += P @ V : 8 dh n-tiles x 2 k16 steps
        #pragma unroll
        for (int nt = 0; nt < 8; nt++) {
            #pragma unroll
            for (int ks = 0; ks < 2; ks++) {
                unsigned bf[2];
                bf[0] = sv2[ks * 8 + c4    ][nt * 8 + r4];
                bf[1] = sv2[ks * 8 + c4 + 4][nt * 8 + r4];
                mma_f16(o[nt], pa[ks], bf);
            }
        }
        __syncwarp();
    }

    // epilogue: normalize and store
    const float inv0 = 1.0f / l0;
    const float inv1 = 1.0f / l1;
    const int rA = qrow0 + r4;
    const int rB = rA + 8;
    float* oA = out + ((size_t)(b * SS + rA)) * DD + h * DH;
    float* oB = out + ((size_t)(b * SS + rB)) * DD + h * DH;
    #pragma unroll
    for (int nt = 0; nt < 8; nt++) {
        const int d = nt * 8 + 2 * c4;
        *(float2*)(oA + d) = make_float2(o[nt][0] * inv0, o[nt][1] * inv0);
        *(float2*)(oB + d) = make_float2(o[nt][2] * inv1, o[nt][3] * inv1);
    }
}

extern "C" void kernel_launch(void* const* d_in, const int* in_sizes, int n_in,
                              void* d_out, int out_size)
{
    const float* x  = (const float*)d_in[0];
    const float* Wq = (const float*)d_in[1];
    const float* bq = (const float*)d_in[2];
    const float* Wk = (const float*)d_in[3];
    const float* bk = (const float*)d_in[4];
    const float* Wv = (const float*)d_in[5];
    const float* bv = (const float*)d_in[6];
    float* out = (float*)d_out;

    dim3 gg(DD / 128, (BB * SS) / 128);   // (8, 128)
    qkv_gemm<<<gg, 256>>>(x, Wq, bq, 0);
    qkv_gemm<<<gg, 256>>>(x, Wk, bk, 1);
    qkv_gemm<<<gg, 256>>>(x, Wv, bv, 2);

    dim3 ga(SS / 64, BB * HH);            // (16, 256)
    attn_kernel<<<ga, 128>>>(out);
}

// round 11
// speedup vs baseline: 2.1036x; 1.3739x over previous
#include <cuda_runtime.h>
#include <cuda_fp16.h>
#include <math.h>

#define BB 16
#define SS 1024
#define DD 1024
#define HH 16
#define DH 64

// Scratch for Q, K, V in head-split layout [B, H, S, Dh] (fp32; attention
// converts to fp16 at staging, applying the 1/8 score scale to Q).
__device__ float g_q[BB * HH * SS * DH];
__device__ float g_k[BB * HH * SS * DH];
__device__ float g_v[BB * HH * SS * DH];

// ---------------------------------------------------------------------------
// d += a @ b   (m16n8k16 fp16 inputs, fp32 accumulate)
// ---------------------------------------------------------------------------
__device__ __forceinline__ void mma_f16(float* d, const unsigned* a, const unsigned* b) {
    asm volatile(
        "mma.sync.aligned.m16n8k16.row.col.f32.f16.f16.f32 "
        "{%0,%1,%2,%3},{%4,%5,%6,%7},{%8,%9},{%0,%1,%2,%3};"
        : "+f"(d[0]), "+f"(d[1]), "+f"(d[2]), "+f"(d[3])
        : "r"(a[0]), "r"(a[1]), "r"(a[2]), "r"(a[3]), "r"(b[0]), "r"(b[1]));
}

__device__ __forceinline__ unsigned h2u(__half2 h) {
    return *(unsigned*)&h;
}

// ---------------------------------------------------------------------------
// QKV projection: Y = X @ W^T + b (fp32 out). fp16 m16n8k16 mma.
// BM=BN=128, BK=32, 256 threads (8 warps as 4x2), warp tile 32x64.
// Coalesced loads (R2 map: 8 lanes cover one 128B row segment); fp16 smem
// stride 40 halfs (fragment LDS bank-verified conflict-free).
// ---------------------------------------------------------------------------
__global__ __launch_bounds__(256)
void qkv_gemm(const float* __restrict__ X, const float* __restrict__ W,
              const float* __restrict__ bias, int which)
{
    __shared__ __half sa[128][40];   // [m][k]
    __shared__ __half sb[128][40];   // [n][k]

    float* __restrict__ Y = (which == 0) ? g_q : (which == 1) ? g_k : g_v;

    const int tid  = threadIdx.x;
    const int lane = tid & 31;
    const int warp = tid >> 5;
    const int wm   = (warp & 3) * 32;
    const int wn   = (warp >> 2) * 64;
    const int m0   = blockIdx.y * 128;
    const int n0   = blockIdx.x * 128;

    // coalesced load map (R2): 8 threads per row, 4 rows/thread spaced 32
    const int lr = tid >> 3;        // 0..31
    const int lc = (tid & 7) * 4;   // 0,4,...,28

    const int r4 = lane >> 2;
    const int c4 = lane & 3;

    float acc[2][8][4];
    #pragma unroll
    for (int i = 0; i < 2; i++)
        #pragma unroll
        for (int j = 0; j < 8; j++)
            #pragma unroll
            for (int c = 0; c < 4; c++) acc[i][j][c] = 0.0f;

    for (int k0 = 0; k0 < DD; k0 += 32) {
        float4 va[4], vb[4];
        #pragma unroll
        for (int i = 0; i < 4; i++) {
            va[i] = *(const float4*)(X + (size_t)(m0 + lr + 32 * i) * DD + k0 + lc);
            vb[i] = *(const float4*)(W + (size_t)(n0 + lr + 32 * i) * DD + k0 + lc);
        }
        __syncthreads();   // previous iteration's mma done reading smem
        #pragma unroll
        for (int i = 0; i < 4; i++) {
            uint2 ua = make_uint2(h2u(__floats2half2_rn(va[i].x, va[i].y)),
                                  h2u(__floats2half2_rn(va[i].z, va[i].w)));
            uint2 ub = make_uint2(h2u(__floats2half2_rn(vb[i].x, vb[i].y)),
                                  h2u(__floats2half2_rn(vb[i].z, vb[i].w)));
            *(uint2*)&sa[lr + 32 * i][lc] = ua;
            *(uint2*)&sb[lr + 32 * i][lc] = ub;
        }
        __syncthreads();

        #pragma unroll
        for (int ks = 0; ks < 2; ks++) {          // 2 x k16 per BK=32
            const int kk = ks * 16 + 2 * c4;
            unsigned af[2][4];
            #pragma unroll
            for (int mt = 0; mt < 2; mt++) {
                const int rb = wm + mt * 16;
                af[mt][0] = *(const unsigned*)&sa[rb + r4    ][kk    ];
                af[mt][1] = *(const unsigned*)&sa[rb + r4 + 8][kk    ];
                af[mt][2] = *(const unsigned*)&sa[rb + r4    ][kk + 8];
                af[mt][3] = *(const unsigned*)&sa[rb + r4 + 8][kk + 8];
            }
            #pragma unroll
            for (int nt = 0; nt < 8; nt++) {
                const int cb = wn + nt * 8;
                unsigned bf[2];
                bf[0] = *(const unsigned*)&sb[cb + r4][kk    ];
                bf[1] = *(const unsigned*)&sb[cb + r4][kk + 8];
                mma_f16(acc[0][nt], af[0], bf);
                mma_f16(acc[1][nt], af[1], bf);
            }
        }
    }

    // Epilogue: bias + head-split scatter (fp32).
    #pragma unroll
    for (int mt = 0; mt < 2; mt++) {
        const int mA = m0 + wm + mt * 16 + r4;
        const int mB = mA + 8;
        const int bA = mA >> 10, sA_ = mA & 1023;
        const int bB = mB >> 10, sB_ = mB & 1023;
        #pragma unroll
        for (int nt = 0; nt < 8; nt++) {
            const int col = n0 + wn + nt * 8 + 2 * c4;
            const int h = col >> 6, d = col & 63;
            const float b0 = bias[col], b1 = bias[col + 1];
            float2 vA = make_float2(acc[mt][nt][0] + b0, acc[mt][nt][1] + b1);
            float2 vB = make_float2(acc[mt][nt][2] + b0, acc[mt][nt][3] + b1);
            *(float2*)(Y + (((size_t)(bA * HH + h) * SS + sA_) * DH) + d) = vA;
            *(float2*)(Y + (((size_t)(bB * HH + h) * SS + sB_) * DH) + d) = vB;
        }
    }
}

// ---------------------------------------------------------------------------
// Flash attention, fp16 m16n8k16 mma — byte-identical to R10 (measured 428us).
// Block = 128 thr (4 warps), 16 q-rows per warp, BC=32, Dh=64.
// ---------------------------------------------------------------------------
__global__ __launch_bounds__(128)
void attn_kernel(float* __restrict__ out)
{
    __shared__ __half sk[32][72];
    __shared__ unsigned sv2[16][72];
    __shared__ __half sp[4][16][72];

    const int tid  = threadIdx.x;
    const int lane = tid & 31;
    const int warp = tid >> 5;
    const int bh   = blockIdx.y;
    const int b    = bh >> 4;
    const int h    = bh & 15;
    const int qrow0 = blockIdx.x * 64 + warp * 16;

    const int r4 = lane >> 2;
    const int c4 = lane & 3;

    const float* Qb = g_q + (size_t)bh * SS * DH;
    const float* Kb = g_k + (size_t)bh * SS * DH;
    const float* Vb = g_v + (size_t)bh * SS * DH;

    // stage Q (x 0.125, fp16) into sp[warp], then load fragments to registers
    {
        #pragma unroll
        for (int i = 0; i < 8; i++) {
            const int idx = lane + i * 32;          // 0..255
            const int row = idx >> 4;               // 0..15
            const int cc  = (idx & 15) * 4;
            float4 t = *(const float4*)(Qb + (size_t)(qrow0 + row) * DH + cc);
            unsigned h0 = h2u(__floats2half2_rn(t.x * 0.125f, t.y * 0.125f));
            unsigned h1 = h2u(__floats2half2_rn(t.z * 0.125f, t.w * 0.125f));
            *(uint2*)&sp[warp][row][cc] = make_uint2(h0, h1);
        }
    }
    __syncwarp();
    unsigned qa[4][4];                              // 4 k16 steps over Dh=64
    #pragma unroll
    for (int ks = 0; ks < 4; ks++) {
        const int kk = ks * 16 + 2 * c4;
        qa[ks][0] = *(const unsigned*)&sp[warp][r4    ][kk    ];
        qa[ks][1] = *(const unsigned*)&sp[warp][r4 + 8][kk    ];
        qa[ks][2] = *(const unsigned*)&sp[warp][r4    ][kk + 8];
        qa[ks][3] = *(const unsigned*)&sp[warp][r4 + 8][kk + 8];
    }
    __syncwarp();

    float o[8][4];
    #pragma unroll
    for (int nt = 0; nt < 8; nt++)
        #pragma unroll
        for (int c = 0; c < 4; c++) o[nt][c] = 0.0f;
    float m0v = -INFINITY, m1v = -INFINITY;
    float l0 = 0.0f, l1 = 0.0f;

    for (int t0 = 0; t0 < SS; t0 += 32) {
        __syncthreads();
        // K: thread -> (row, 4 d's): cvt + 8B store
        #pragma unroll
        for (int i = 0; i < 4; i++) {
            const int idx = tid + i * 128;          // 0..511
            const int row = idx >> 4;               // 0..31
            const int cc  = (idx & 15) * 4;
            float4 kt4 = *(const float4*)(Kb + (size_t)(t0 + row) * DH + cc);
            unsigned h0 = h2u(__floats2half2_rn(kt4.x, kt4.y));
            unsigned h1 = h2u(__floats2half2_rn(kt4.z, kt4.w));
            *(uint2*)&sk[row][cc] = make_uint2(h0, h1);
        }
        // V: thread -> (kv pair kvp = tid>>3, 8 d's): pair-interleave, 2x16B store
        {
            const int kvp = tid >> 3;               // 0..15
            const int d0  = (tid & 7) * 8;
            const float* v0 = Vb + (size_t)(t0 + 2 * kvp) * DH + d0;
            const float* v1 = v0 + DH;
            float4 a0 = *(const float4*)(v0);
            float4 a1 = *(const float4*)(v0 + 4);
            float4 b0 = *(const float4*)(v1);
            float4 b1 = *(const float4*)(v1 + 4);
            uint4 w0, w1;
            w0.x = h2u(__floats2half2_rn(a0.x, b0.x));
            w0.y = h2u(__floats2half2_rn(a0.y, b0.y));
            w0.z = h2u(__floats2half2_rn(a0.z, b0.z));
            w0.w = h2u(__floats2half2_rn(a0.w, b0.w));
            w1.x = h2u(__floats2half2_rn(a1.x, b1.x));
            w1.y = h2u(__floats2half2_rn(a1.y, b1.y));
            w1.z = h2u(__floats2half2_rn(a1.z, b1.z));
            w1.w = h2u(__floats2half2_rn(a1.w, b1.w));
            *(uint4*)&sv2[kvp][d0]     = w0;
            *(uint4*)&sv2[kvp][d0 + 4] = w1;
        }
        __syncthreads();

        // S = Q @ K^T : 4 kv n-tiles x 4 k16 steps
        float s[4][4];
        #pragma unroll
        for (int nt = 0; nt < 4; nt++) {
            #pragma unroll
            for (int c = 0; c < 4; c++) s[nt][c] = 0.0f;
            #pragma unroll
            for (int ks = 0; ks < 4; ks++) {
                const int kk = ks * 16 + 2 * c4;
                unsigned bf[2];
                bf[0] = *(const unsigned*)&sk[nt * 8 + r4][kk    ];
                bf[1] = *(const unsigned*)&sk[nt * 8 + r4][kk + 8];
                mma_f16(s[nt], qa[ks], bf);
            }
        }

        // online softmax (fp32)
        float tm0 = -INFINITY, tm1 = -INFINITY;
        #pragma unroll
        for (int nt = 0; nt < 4; nt++) {
            tm0 = fmaxf(tm0, fmaxf(s[nt][0], s[nt][1]));
            tm1 = fmaxf(tm1, fmaxf(s[nt][2], s[nt][3]));
        }
        tm0 = fmaxf(tm0, __shfl_xor_sync(0xffffffffu, tm0, 1));
        tm0 = fmaxf(tm0, __shfl_xor_sync(0xffffffffu, tm0, 2));
        tm1 = fmaxf(tm1, __shfl_xor_sync(0xffffffffu, tm1, 1));
        tm1 = fmaxf(tm1, __shfl_xor_sync(0xffffffffu, tm1, 2));

        const float mn0 = fmaxf(m0v, tm0);
        const float mn1 = fmaxf(m1v, tm1);
        const float sc0 = __expf(m0v - mn0);
        const float sc1 = __expf(m1v - mn1);
        m0v = mn0; m1v = mn1;

        float ps0 = 0.0f, ps1 = 0.0f;
        #pragma unroll
        for (int nt = 0; nt < 4; nt++) {
            s[nt][0] = __expf(s[nt][0] - mn0);
            s[nt][1] = __expf(s[nt][1] - mn0);
            s[nt][2] = __expf(s[nt][2] - mn1);
            s[nt][3] = __expf(s[nt][3] - mn1);
            ps0 += s[nt][0] + s[nt][1];
            ps1 += s[nt][2] + s[nt][3];
        }
        ps0 += __shfl_xor_sync(0xffffffffu, ps0, 1);
        ps0 += __shfl_xor_sync(0xffffffffu, ps0, 2);
        ps1 += __shfl_xor_sync(0xffffffffu, ps1, 1);
        ps1 += __shfl_xor_sync(0xffffffffu, ps1, 2);
        l0 = l0 * sc0 + ps0;
        l1 = l1 * sc1 + ps1;

        #pragma unroll
        for (int nt = 0; nt < 8; nt++) {
            o[nt][0] *= sc0; o[nt][1] *= sc0;
            o[nt][2] *= sc1; o[nt][3] *= sc1;
        }

        // P (fp16) -> warp-private smem; reload as A fragments
        #pragma unroll
        for (int nt = 0; nt < 4; nt++) {
            const int pc = nt * 8 + 2 * c4;
            *(unsigned*)&sp[warp][r4    ][pc] = h2u(__floats2half2_rn(s[nt][0], s[nt][1]));
            *(unsigned*)&sp[warp][r4 + 8][pc] = h2u(__floats2half2_rn(s[nt][2], s[nt][3]));
        }
        __syncwarp();

        unsigned pa[2][4];                          // 2 k16 steps over kv=32
        #pragma unroll
        for (int ks = 0; ks < 2; ks++) {
            const int kk = ks * 16 + 2 * c4;
            pa[ks][0] = *(const unsigned*)&sp[warp][r4    ][kk    ];
            pa[ks][1] = *(const unsigned*)&sp[warp][r4 + 8][kk    ];
            pa[ks][2] = *(const unsigned*)&sp[warp][r4    ][kk + 8];
            pa[ks][3] = *(const unsigned*)&sp[warp][r4 + 8][kk + 8];
        }

        // O += P @ V : 8 dh n-tiles x 2 k16 steps
        #pragma unroll
        for (int nt = 0; nt < 8; nt++) {
            #pragma unroll
            for (int ks = 0; ks < 2; ks++) {
                unsigned bf[2];
                bf[0] = sv2[ks * 8 + c4    ][nt * 8 + r4];
                bf[1] = sv2[ks * 8 + c4 + 4][nt * 8 + r4];
                mma_f16(o[nt], pa[ks], bf);
            }
        }
        __syncwarp();
    }

    // epilogue: normalize and store
    const float inv0 = 1.0f / l0;
    const float inv1 = 1.0f / l1;
    const int rA = qrow0 + r4;
    const int rB = rA + 8;
    float* oA = out + ((size_t)(b * SS + rA)) * DD + h * DH;
    float* oB = out + ((size_t)(b * SS + rB)) * DD + h * DH;
    #pragma unroll
    for (int nt = 0; nt < 8; nt++) {
        const int d = nt * 8 + 2 * c4;
        *(float2*)(oA + d) = make_float2(o[nt][0] * inv0, o[nt][1] * inv0);
        *(float2*)(oB + d) = make_float2(o[nt][2] * inv1, o[nt][3] * inv1);
    }
}

extern "C" void kernel_launch(void* const* d_in, const int* in_sizes, int n_in,
                              void* d_out, int out_size)
{
    const float* x  = (const float*)d_in[0];
    const float* Wq = (const float*)d_in[1];
    const float* bq = (const float*)d_in[2];
    const float* Wk = (const float*)d_in[3];
    const float* bk = (const float*)d_in[4];
    const float* Wv = (const float*)d_in[5];
    const float* bv = (const float*)d_in[6];
    float* out = (float*)d_out;

    dim3 gg(DD / 128, (BB * SS) / 128);   // (8, 128)
    qkv_gemm<<<gg, 256>>>(x, Wq, bq, 0);
    qkv_gemm<<<gg, 256>>>(x, Wk, bk, 1);
    qkv_gemm<<<gg, 256>>>(x, Wv, bv, 2);

    dim3 ga(SS / 64, BB * HH);            // (16, 256)
    attn_kernel<<<ga, 128>>>(out);
}